// round 13
// baseline (speedup 1.0000x reference)
#include <cuda_runtime.h>
#include <cuda_bf16.h>
#include <math.h>
#include <stdint.h>

#define V_   4
#define T_   4
#define NS_  100000
#define NH_  12288
#define E_   100000
#define H_   64
#define ET_  (V_ * T_)
// lrelu(y) = max(y, 0.01y) = 0.505*y + 0.495*|y|
#define C_A  0.505f
#define C_B  0.495f

#define EDGES_PER_BLK   1024
#define DEG_BLK_PER_ET  98            // ceil(E_/EDGES_PER_BLK)
#define DEG_BLKS        (ET_ * DEG_BLK_PER_ET)     // 1568
#define BLKS_PER_V      (DEG_BLK_PER_ET * T_)      // 392

// ---------------- scratch (static __device__, no allocation) ----------------
__device__ int    g_deg_out[ET_ * NS_];
__device__ int    g_deg_in [ET_ * NH_];
__device__ float  g_s      [ET_ * NH_ * T_];   // (et, n, t), t innermost
__device__ float4 g_xT     [V_ * NS_];
__device__ int    g_done_v [V_];               // degree-phase completion per v

// ---------------- packed f32x2 helpers ----------------
__device__ __forceinline__ unsigned long long pk2(float lo, float hi) {
    unsigned long long r;
    asm("mov.b64 %0, {%1, %2};" : "=l"(r) : "f"(lo), "f"(hi));
    return r;
}
__device__ __forceinline__ void upk2(unsigned long long v, float& lo, float& hi) {
    asm("mov.b64 {%0, %1}, %2;" : "=f"(lo), "=f"(hi) : "l"(v));
}
__device__ __forceinline__ unsigned long long fma2(unsigned long long a,
                                                   unsigned long long b,
                                                   unsigned long long c) {
    unsigned long long d;
    asm("fma.rn.f32x2 %0, %1, %2, %3;" : "=l"(d) : "l"(a), "l"(b), "l"(c));
    return d;
}

__device__ __forceinline__ void red_v4(float* p, float4 xv, float ns) {
    asm volatile("red.global.add.v4.f32 [%0], {%1, %2, %3, %4};"
                 :: "l"(p), "f"(xv.x * ns), "f"(xv.y * ns),
                    "f"(xv.z * ns), "f"(xv.w * ns) : "memory");
}

// ---------------- fused degrees + transpose + gated scatter ----------------
// bids [0, DEG_BLKS):        degree counting (one etype per block) + x transpose share
// bids [DEG_BLKS, 2*DEG_BLKS): scatter, gated on done_v[v] == BLKS_PER_V
__global__ void __launch_bounds__(256) k_graph(const float* __restrict__ x,
                                               const int4* __restrict__ src4,
                                               const int4* __restrict__ dst4) {
    int bid = blockIdx.x;
    int tid = threadIdx.x;

    if (bid < DEG_BLKS) {
        // ---- degree phase ----
        int et     = bid / DEG_BLK_PER_ET;
        int blk_in = bid - et * DEG_BLK_PER_ET;
        int v      = et >> 2;
        int e0     = blk_in * EDGES_PER_BLK;            // within etype
        int nedge  = min(EDGES_PER_BLK, E_ - e0);

        int g = tid;                                     // group of 4 edges
        if (g * 4 < nedge) {
            int gi = (et * E_ + e0) / 4 + g;
            int4 s = src4[gi];
            int4 d = dst4[gi];
            int* po = &g_deg_out[et * NS_];
            int* pi = &g_deg_in [et * NH_];
            atomicAdd(po + s.x, 1); atomicAdd(po + s.y, 1);
            atomicAdd(po + s.z, 1); atomicAdd(po + s.w, 1);
            atomicAdd(pi + d.x, 1); atomicAdd(pi + d.y, 1);
            atomicAdd(pi + d.z, 1); atomicAdd(pi + d.w, 1);
        }

        // ---- transpose share: 256 entries of xT[v] per block ----
        int j = (bid % BLKS_PER_V) * 256 + tid;          // 392*256 = 100352 >= NS_
        if (j < NS_) {
            float a0 = x[(v * T_ + 0) * NS_ + j];
            float a1 = x[(v * T_ + 1) * NS_ + j];
            float a2 = x[(v * T_ + 2) * NS_ + j];
            float a3 = x[(v * T_ + 3) * NS_ + j];
            float4 r;
            r.x = isnan(a0) ? 0.0f : a0;
            r.y = isnan(a1) ? 0.0f : a1;
            r.z = isnan(a2) ? 0.0f : a2;
            r.w = isnan(a3) ? 0.0f : a3;
            g_xT[v * NS_ + j] = r;
        }

        __threadfence();                                  // publish REDs + xT stores
        __syncthreads();
        if (tid == 0) atomicAdd(&g_done_v[v], 1);
    } else {
        // ---- scatter phase (gated) ----
        int b2     = bid - DEG_BLKS;
        int et     = b2 / DEG_BLK_PER_ET;
        int blk_in = b2 - et * DEG_BLK_PER_ET;
        int v      = et >> 2;
        int e0     = blk_in * EDGES_PER_BLK;
        int nedge  = min(EDGES_PER_BLK, E_ - e0);

        if (tid == 0) {
            while (atomicAdd(&g_done_v[v], 0) < BLKS_PER_V) { /* spin */ }
        }
        __syncthreads();
        __threadfence();                                  // acquire

        int g = tid;
        if (g * 4 < nedge) {
            int gi = (et * E_ + e0) / 4 + g;
            int4 s = src4[gi];
            int4 d = dst4[gi];

            int dg0 = __ldg(&g_deg_out[et * NS_ + s.x]);
            int dg1 = __ldg(&g_deg_out[et * NS_ + s.y]);
            int dg2 = __ldg(&g_deg_out[et * NS_ + s.z]);
            int dg3 = __ldg(&g_deg_out[et * NS_ + s.w]);
            float4 x0 = __ldg(&g_xT[v * NS_ + s.x]);
            float4 x1 = __ldg(&g_xT[v * NS_ + s.y]);
            float4 x2 = __ldg(&g_xT[v * NS_ + s.z]);
            float4 x3 = __ldg(&g_xT[v * NS_ + s.w]);

            float n0 = rsqrtf(fmaxf((float)dg0, 1.0f));
            float n1 = rsqrtf(fmaxf((float)dg1, 1.0f));
            float n2 = rsqrtf(fmaxf((float)dg2, 1.0f));
            float n3 = rsqrtf(fmaxf((float)dg3, 1.0f));

            float* base = &g_s[et * NH_ * T_];
            red_v4(base + d.x * T_, x0, n0);
            red_v4(base + d.y * T_, x1, n1);
            red_v4(base + d.z * T_, x2, n2);
            red_v4(base + d.w * T_, x3, n3);
        }
    }
}

// ---------------- epilogue (packed f32x2, smem-staged z, W/b in regs) ----------------
#define NPB 8
__global__ void __launch_bounds__(256) k_epilogue(const float4* __restrict__ W4,
                                                  const float4* __restrict__ b4,
                                                  float4* __restrict__ out4) {
    __shared__ float4 zsm[ET_ * NPB];

    int tx = threadIdx.x;
    int n0 = blockIdx.x * NPB;

    if (tx < ET_ * NPB) {
        int et = tx >> 3;
        int k  = tx & (NPB - 1);
        int n  = n0 + k;
        float nd = rsqrtf(fmaxf((float)__ldg(&g_deg_in[et * NH_ + n]), 1.0f));
        float4 sv = *(const float4*)&g_s[(et * NH_ + n) * T_];
        sv.x *= nd; sv.y *= nd; sv.z *= nd; sv.w *= nd;
        zsm[tx] = sv;
    }

    int q = tx & 15;
    int t = (tx >> 4) & 3;
    int v = tx >> 6;

    unsigned long long w01[T_], w23[T_], b01[T_], b23[T_];
#pragma unroll
    for (int tp = 0; tp < T_; tp++) {
        int et = v * T_ + tp;
        float4 w  = W4[et * (H_ / 4) + q];
        float4 bb = b4[et * (H_ / 4) + q];
        w01[tp] = pk2(w.x, w.y);   w23[tp] = pk2(w.z, w.w);
        b01[tp] = pk2(bb.x, bb.y); b23[tp] = pk2(bb.z, bb.w);
    }
    const unsigned long long CA = pk2(C_A, C_A);
    const unsigned long long CB = pk2(C_B, C_B);
    const unsigned long long ABSM = 0x7fffffff7fffffffULL;

    __syncthreads();

#pragma unroll
    for (int k = 0; k < NPB; k++) {
        unsigned long long acc01 = 0ULL, acc23 = 0ULL;
#pragma unroll
        for (int tp = 0; tp < T_; tp++) {
            int et = v * T_ + tp;
            float sv = ((const float*)&zsm[et * NPB + k])[t];
            unsigned long long sv2 = pk2(sv, sv);
            unsigned long long y01 = fma2(sv2, w01[tp], b01[tp]);
            unsigned long long y23 = fma2(sv2, w23[tp], b23[tp]);
            acc01 = fma2(CA, y01, acc01);
            acc23 = fma2(CA, y23, acc23);
            acc01 = fma2(CB, y01 & ABSM, acc01);
            acc23 = fma2(CB, y23 & ABSM, acc23);
        }
        float4 r;
        upk2(acc01, r.x, r.y);
        upk2(acc23, r.z, r.w);
        int n = n0 + k;
        out4[((n * V_ + v) * T_ + t) * (H_ / 4) + q] = r;
    }
}

// ---------------- launch ----------------
extern "C" void kernel_launch(void* const* d_in, const int* in_sizes, int n_in,
                              void* d_out, int out_size) {
    const float* x = (const float*)d_in[0];
    const float* W = (const float*)d_in[1];
    const float* b = (const float*)d_in[2];
    const int* src = (const int*)d_in[3];
    const int* dst = (const int*)d_in[4];

    void* p_deg_out; cudaGetSymbolAddress(&p_deg_out, g_deg_out);
    void* p_deg_in;  cudaGetSymbolAddress(&p_deg_in,  g_deg_in);
    void* p_s;       cudaGetSymbolAddress(&p_s,       g_s);
    void* p_done;    cudaGetSymbolAddress(&p_done,    g_done_v);
    cudaMemsetAsync(p_deg_out, 0, ET_ * NS_ * sizeof(int));
    cudaMemsetAsync(p_deg_in,  0, ET_ * NH_ * sizeof(int));
    cudaMemsetAsync(p_s,       0, ET_ * NH_ * T_ * sizeof(float));
    cudaMemsetAsync(p_done,    0, V_ * sizeof(int));

    k_graph<<<2 * DEG_BLKS, 256>>>(x, (const int4*)src, (const int4*)dst);

    k_epilogue<<<NH_ / NPB, 256>>>(
        (const float4*)W, (const float4*)b, (float4*)d_out);
}

// round 15
// speedup vs baseline: 1.1811x; 1.1811x over previous
#include <cuda_runtime.h>
#include <cuda_bf16.h>
#include <math.h>
#include <stdint.h>

#define V_   4
#define T_   4
#define NS_  100000
#define NH_  12288
#define E_   100000
#define H_   64
#define ET_  (V_ * T_)
// lrelu(y) = max(y, 0.01y) = 0.505*y + 0.495*|y|
#define C_A  0.505f
#define C_B  0.495f

// ---------------- scratch (static __device__, no allocation) ----------------
__device__ int    g_deg_out[ET_ * NS_];        // counts per (et, s)
__device__ int    g_deg_in [ET_ * NH_];        // counts per (et, n)
__device__ float  g_s      [ET_ * NH_ * T_];   // (et, n, t), t innermost
__device__ float4 g_xT     [V_ * NS_];         // xT[v][s] over t, nan-cleaned

// ---------------- packed f32x2 helpers ----------------
__device__ __forceinline__ unsigned long long pk2(float lo, float hi) {
    unsigned long long r;
    asm("mov.b64 %0, {%1, %2};" : "=l"(r) : "f"(lo), "f"(hi));
    return r;
}
__device__ __forceinline__ void upk2(unsigned long long v, float& lo, float& hi) {
    asm("mov.b64 {%0, %1}, %2;" : "=f"(lo), "=f"(hi) : "l"(v));
}
__device__ __forceinline__ unsigned long long fma2(unsigned long long a,
                                                   unsigned long long b,
                                                   unsigned long long c) {
    unsigned long long d;
    asm("fma.rn.f32x2 %0, %1, %2, %3;" : "=l"(d) : "l"(a), "l"(b), "l"(c));
    return d;
}

// ---------------- kernel 1: init (zero scratch + transpose x) — R8 proven ----------------
__global__ void k_init(const float* __restrict__ x) {
    int i = blockIdx.x * blockDim.x + threadIdx.x;
    int stride = gridDim.x * blockDim.x;
    const int4 z4 = make_int4(0, 0, 0, 0);
    for (int j = i; j < ET_ * NS_ / 4; j += stride)
        ((int4*)g_deg_out)[j] = z4;
    for (int j = i; j < ET_ * NH_ / 4; j += stride)
        ((int4*)g_deg_in)[j] = z4;
    for (int j = i; j < ET_ * NH_ * T_ / 4; j += stride)
        ((int4*)g_s)[j] = z4;
    for (int j = i; j < V_ * NS_; j += stride) {
        int v = j / NS_;
        int s = j - v * NS_;
        float a0 = x[(v * T_ + 0) * NS_ + s];
        float a1 = x[(v * T_ + 1) * NS_ + s];
        float a2 = x[(v * T_ + 2) * NS_ + s];
        float a3 = x[(v * T_ + 3) * NS_ + s];
        float4 r;
        r.x = isnan(a0) ? 0.0f : a0;
        r.y = isnan(a1) ? 0.0f : a1;
        r.z = isnan(a2) ? 0.0f : a2;
        r.w = isnan(a3) ? 0.0f : a3;
        g_xT[j] = r;
    }
}

// ---------------- kernel 2: degree counts (8 edges/thread, loads batched) ----------------
__global__ void k_degrees(const int4* __restrict__ src4,
                          const int4* __restrict__ dst4) {
    int i = blockIdx.x * blockDim.x + threadIdx.x;   // over ET_*E_/8
    if (i >= ET_ * E_ / 8) return;
    int et = (i * 8) / E_;                           // 8-groups never straddle etypes
    int4 s0 = src4[2 * i], s1 = src4[2 * i + 1];     // batch all index loads first
    int4 d0 = dst4[2 * i], d1 = dst4[2 * i + 1];
    int* po = &g_deg_out[et * NS_];
    int* pi = &g_deg_in [et * NH_];
    atomicAdd(po + s0.x, 1); atomicAdd(po + s0.y, 1);
    atomicAdd(po + s0.z, 1); atomicAdd(po + s0.w, 1);
    atomicAdd(po + s1.x, 1); atomicAdd(po + s1.y, 1);
    atomicAdd(po + s1.z, 1); atomicAdd(po + s1.w, 1);
    atomicAdd(pi + d0.x, 1); atomicAdd(pi + d0.y, 1);
    atomicAdd(pi + d0.z, 1); atomicAdd(pi + d0.w, 1);
    atomicAdd(pi + d1.x, 1); atomicAdd(pi + d1.y, 1);
    atomicAdd(pi + d1.z, 1); atomicAdd(pi + d1.w, 1);
}

// ---------------- kernel 3: normalized scatter (8 edges/thread, MLP 16) ----------------
__device__ __forceinline__ void red_v4(float* p, float4 xv, float ns) {
    asm volatile("red.global.add.v4.f32 [%0], {%1, %2, %3, %4};"
                 :: "l"(p), "f"(xv.x * ns), "f"(xv.y * ns),
                    "f"(xv.z * ns), "f"(xv.w * ns) : "memory");
}

__global__ void k_scatter(const int4* __restrict__ src4,
                          const int4* __restrict__ dst4) {
    int i = blockIdx.x * blockDim.x + threadIdx.x;   // over ET_*E_/8
    if (i >= ET_ * E_ / 8) return;
    int et = (i * 8) / E_;
    int v  = et >> 2;
    int4 s0 = src4[2 * i], s1 = src4[2 * i + 1];
    int4 d0 = dst4[2 * i], d1 = dst4[2 * i + 1];

    const int*    dgb = &g_deg_out[et * NS_];
    const float4* xb  = &g_xT[v * NS_];

    // batch all 16 gathers before any consumption
    int dg0 = __ldg(dgb + s0.x), dg1 = __ldg(dgb + s0.y);
    int dg2 = __ldg(dgb + s0.z), dg3 = __ldg(dgb + s0.w);
    int dg4 = __ldg(dgb + s1.x), dg5 = __ldg(dgb + s1.y);
    int dg6 = __ldg(dgb + s1.z), dg7 = __ldg(dgb + s1.w);
    float4 x0 = __ldg(xb + s0.x), x1 = __ldg(xb + s0.y);
    float4 x2 = __ldg(xb + s0.z), x3 = __ldg(xb + s0.w);
    float4 x4 = __ldg(xb + s1.x), x5 = __ldg(xb + s1.y);
    float4 x6 = __ldg(xb + s1.z), x7 = __ldg(xb + s1.w);

    float n0 = rsqrtf(fmaxf((float)dg0, 1.0f));
    float n1 = rsqrtf(fmaxf((float)dg1, 1.0f));
    float n2 = rsqrtf(fmaxf((float)dg2, 1.0f));
    float n3 = rsqrtf(fmaxf((float)dg3, 1.0f));
    float n4 = rsqrtf(fmaxf((float)dg4, 1.0f));
    float n5 = rsqrtf(fmaxf((float)dg5, 1.0f));
    float n6 = rsqrtf(fmaxf((float)dg6, 1.0f));
    float n7 = rsqrtf(fmaxf((float)dg7, 1.0f));

    float* base = &g_s[et * NH_ * T_];
    red_v4(base + d0.x * T_, x0, n0);
    red_v4(base + d0.y * T_, x1, n1);
    red_v4(base + d0.z * T_, x2, n2);
    red_v4(base + d0.w * T_, x3, n3);
    red_v4(base + d1.x * T_, x4, n4);
    red_v4(base + d1.y * T_, x5, n5);
    red_v4(base + d1.z * T_, x6, n6);
    red_v4(base + d1.w * T_, x7, n7);
}

// ---------------- kernel 4: epilogue (packed f32x2 — measured 11.6us in R13) ----------------
#define NPB 8
__global__ void __launch_bounds__(256) k_epilogue(const float4* __restrict__ W4,
                                                  const float4* __restrict__ b4,
                                                  float4* __restrict__ out4) {
    __shared__ float4 zsm[ET_ * NPB];

    int tx = threadIdx.x;
    int n0 = blockIdx.x * NPB;

    if (tx < ET_ * NPB) {
        int et = tx >> 3;
        int k  = tx & (NPB - 1);
        int n  = n0 + k;
        float nd = rsqrtf(fmaxf((float)__ldg(&g_deg_in[et * NH_ + n]), 1.0f));
        float4 sv = *(const float4*)&g_s[(et * NH_ + n) * T_];
        sv.x *= nd; sv.y *= nd; sv.z *= nd; sv.w *= nd;
        zsm[tx] = sv;
    }

    int q = tx & 15;
    int t = (tx >> 4) & 3;
    int v = tx >> 6;

    unsigned long long w01[T_], w23[T_], b01[T_], b23[T_];
#pragma unroll
    for (int tp = 0; tp < T_; tp++) {
        int et = v * T_ + tp;
        float4 w  = W4[et * (H_ / 4) + q];
        float4 bb = b4[et * (H_ / 4) + q];
        w01[tp] = pk2(w.x, w.y);   w23[tp] = pk2(w.z, w.w);
        b01[tp] = pk2(bb.x, bb.y); b23[tp] = pk2(bb.z, bb.w);
    }
    const unsigned long long CA = pk2(C_A, C_A);
    const unsigned long long CB = pk2(C_B, C_B);
    const unsigned long long ABSM = 0x7fffffff7fffffffULL;

    __syncthreads();

#pragma unroll
    for (int k = 0; k < NPB; k++) {
        unsigned long long acc01 = 0ULL, acc23 = 0ULL;
#pragma unroll
        for (int tp = 0; tp < T_; tp++) {
            int et = v * T_ + tp;
            float sv = ((const float*)&zsm[et * NPB + k])[t];   // LDS broadcast
            unsigned long long sv2 = pk2(sv, sv);
            unsigned long long y01 = fma2(sv2, w01[tp], b01[tp]);
            unsigned long long y23 = fma2(sv2, w23[tp], b23[tp]);
            acc01 = fma2(CA, y01, acc01);
            acc23 = fma2(CA, y23, acc23);
            acc01 = fma2(CB, y01 & ABSM, acc01);
            acc23 = fma2(CB, y23 & ABSM, acc23);
        }
        float4 r;
        upk2(acc01, r.x, r.y);
        upk2(acc23, r.z, r.w);
        int n = n0 + k;
        out4[((n * V_ + v) * T_ + t) * (H_ / 4) + q] = r;       // coalesced
    }
}

// ---------------- launch ----------------
extern "C" void kernel_launch(void* const* d_in, const int* in_sizes, int n_in,
                              void* d_out, int out_size) {
    const float* x = (const float*)d_in[0];
    const float* W = (const float*)d_in[1];
    const float* b = (const float*)d_in[2];
    const int* src = (const int*)d_in[3];
    const int* dst = (const int*)d_in[4];

    const int threads = 256;

    k_init<<<(ET_ * NS_ / 4 + threads - 1) / threads, threads>>>(x);

    k_degrees<<<(ET_ * E_ / 8 + threads - 1) / threads, threads>>>(
        (const int4*)src, (const int4*)dst);

    k_scatter<<<(ET_ * E_ / 8 + threads - 1) / threads, threads>>>(
        (const int4*)src, (const int4*)dst);

    k_epilogue<<<NH_ / NPB, 256>>>(
        (const float4*)W, (const float4*)b, (float4*)d_out);
}